// round 13
// baseline (speedup 1.0000x reference)
#include <cuda_runtime.h>
#include <cuda_fp16.h>

// Problem constants (fixed by the dataset)
#define HH   512
#define WW   1024
#define HOo  512
#define WOo  1024
#define NPIX (HH * WW)          // 524288 input pixels
#define NOUT (HOo * WOo)        // 524288 output cells per plane
#define NPLANE 128              // B*C
#define CPW  2                  // cells per warp (consecutive in x)
#define CELLS_PB 16             // 8 warps x 2 cells per block (one row segment)
#define NTILES (NOUT / CELLS_PB)
#define ROWSLAB 2048            // fixed entry slab per output row (mean ~1024, max ~1150)
#define GATHER_GRID (148 * 8)   // persistent: one wave of CTAs

// ---- static device scratch ----
__device__ __half g_xt[(size_t)NPIX * NPLANE]; // 128MB transposed x [pixel][plane], fp16
__device__ int    g_count[NOUT];               // zero at start; scanA re-zeroes each run
__device__ int    g_off[NOUT];                 // row-local exclusive scan
__device__ int    g_cursor[NOUT];
__device__ int4   g_entry[512 * ROWSLAB];      // 16MB slab-allocated entries

// ---------------------------------------------------------------
// K1: fused transpose + histogram.
// Block = 64 pixels x all 128 planes. Writeout: warp per pixel, lane l
// stores planes 4l..4l+3 as one uint2 -> full 256B row in ONE wavefront.
__global__ __launch_bounds__(256)
void txh_k(const float* __restrict__ x, const float2* __restrict__ smap) {
    __shared__ __half hbuf[64][132];            // stride 132: uint2-aligned, low conflict
    int p0 = blockIdx.x * 64;
    int tid = threadIdx.x;

    // histogram for this block's 64 pixels (anchors always in-bounds)
    if (tid < 64) {
        float2 s = __ldg(&smap[p0 + tid]);
        int x0 = (int)floorf(s.x);
        int y0 = (int)floorf(s.y);
        atomicAdd(&g_count[(y0 << 10) + x0], 1);
    }

    // load fp32, convert, stage transposed
    #pragma unroll
    for (int it = 0; it < 32; it++) {
        int idx = tid + it * 256;               // 0..8191
        int c  = idx >> 6;                      // plane 0..127
        int px = idx & 63;
        hbuf[px][c] = __float2half(__ldg(&x[(size_t)c * NPIX + p0 + px]));
    }
    __syncthreads();

    // store: one warp per pixel, full 256B row per wavefront
    int lane = tid & 31, wid = tid >> 5;
    #pragma unroll
    for (int i = wid; i < 64; i += 8) {
        uint2 v = *reinterpret_cast<uint2*>(&hbuf[i][lane * 4]);
        *reinterpret_cast<uint2*>(&g_xt[(size_t)(p0 + i) * NPLANE + lane * 4]) = v;
    }
}

// K2: per-row (1024 cells) exclusive scan -> row-local offsets + cursors.
// Also zeroes g_count for the next graph replay (self-cleaning).
__global__ __launch_bounds__(1024)
void scanA_k() {
    int tid = threadIdx.x;
    int cell = blockIdx.x * 1024 + tid;         // blockIdx.x = output row y
    int cnt = g_count[cell];
    g_count[cell] = 0;                          // ready for next replay
    int lane = tid & 31, wid = tid >> 5;
    int v = cnt;
    #pragma unroll
    for (int d = 1; d < 32; d <<= 1) {
        int t = __shfl_up_sync(0xFFFFFFFFu, v, d);
        if (lane >= d) v += t;
    }
    __shared__ int wsum[32];
    if (lane == 31) wsum[wid] = v;
    __syncthreads();
    if (wid == 0) {
        int s = wsum[lane];
        #pragma unroll
        for (int d = 1; d < 32; d <<= 1) {
            int t = __shfl_up_sync(0xFFFFFFFFu, s, d);
            if (lane >= d) s += t;
        }
        wsum[lane] = s;
    }
    __syncthreads();
    int excl = v - cnt + (wid ? wsum[wid - 1] : 0);
    g_off[cell] = excl;
    g_cursor[cell] = excl;
}

// K3: scatter one entry per pixel into its row slab
__global__ __launch_bounds__(256)
void scatter_k(const float2* __restrict__ smap) {
    int p = blockIdx.x * blockDim.x + threadIdx.x;
    if (p >= NPIX) return;
    float2 s = __ldg(&smap[p]);
    float x0f = floorf(s.x), y0f = floorf(s.y);
    int x0 = (int)x0f, y0 = (int)y0f;
    float wx = s.x - x0f, wy = s.y - y0f;
    int pos = atomicAdd(&g_cursor[(y0 << 10) + x0], 1) + (y0 << 11);
    g_entry[pos] = make_int4(x0, p, __float_as_int(wx), __float_as_int(wy));
}

// K4: PERSISTENT gather. 1184 resident CTAs loop over all 32768 tile
// segments -> a single CTA wave (kills ~28 wave transitions + per-CTA
// launch/drain that dominated the fixed-grid version). Body identical to
// the R12 winner: warp owns 2 cells x 128 planes in 8 accumulator regs.
__global__ __launch_bounds__(256)
void gather_k(float* __restrict__ out) {
    // NPLANE+4 pad: row stride 528B (divisible by 16) -> aligned float4 staging.
    __shared__ float acc_s[CELLS_PB][NPLANE + 4];
    int tid = threadIdx.x;
    int lane = tid & 31, wid = tid >> 5;            // 8 warps

    #pragma unroll 1
    for (int tile = blockIdx.x; tile < NTILES; tile += GATHER_GRID) {
        int cell0 = tile * CELLS_PB;                // 16-aligned -> one row
        int cy = cell0 >> 10;
        int cx0 = (cell0 & 1023) + wid * CPW;

        float a0[4] = {0.f, 0.f, 0.f, 0.f};         // cell cx0
        float a1[4] = {0.f, 0.f, 0.f, 0.f};         // cell cx0+1

        int xs = max(cx0 - 1, 0);
        int xe = min(cx0 + CPW - 1, WOo - 2);       // anchors exist in [0,1022]

        #pragma unroll
        for (int rr = 0; rr < 2; rr++) {
            int ay = cy - 1 + rr;                   // rr=0: weight wy; rr=1: 1-wy
            if ((unsigned)ay > (unsigned)(HOo - 2)) continue;
            int rb = ay << 10;
            int o0 = __ldg(&g_off[rb + xs]);
            int o1 = __ldg(&g_off[rb + xe + 1]);
            int beg = o0 + (ay << 11);
            int end = o1 + (ay << 11);

            #pragma unroll 2
            for (int i = beg; i < end; i++) {
                int4 e = __ldg(&g_entry[i]);
                uint2 r = __ldg(reinterpret_cast<const uint2*>(
                    &g_xt[(size_t)e.y * NPLANE + lane * 4]));
                float wx = __int_as_float(e.z);
                float wyr = __int_as_float(e.w);
                float wyv = rr ? (1.0f - wyr) : wyr;
                float omx = 1.0f - wx;
                int d = e.x - cx0;                  // -1, 0, 1
                float w0 = (d == 0) ? omx : ((d == -1) ? wx : 0.0f);
                float w1 = (d == 1) ? omx : ((d == 0) ? wx : 0.0f);
                w0 *= wyv;
                w1 *= wyv;
                float2 f0 = __half22float2(*reinterpret_cast<__half2*>(&r.x));
                float2 f1 = __half22float2(*reinterpret_cast<__half2*>(&r.y));
                a0[0] = fmaf(w0, f0.x, a0[0]);
                a0[1] = fmaf(w0, f0.y, a0[1]);
                a0[2] = fmaf(w0, f1.x, a0[2]);
                a0[3] = fmaf(w0, f1.y, a0[3]);
                a1[0] = fmaf(w1, f0.x, a1[0]);
                a1[1] = fmaf(w1, f0.y, a1[1]);
                a1[2] = fmaf(w1, f1.x, a1[2]);
                a1[3] = fmaf(w1, f1.y, a1[3]);
            }
        }

        // stage to shared (plane = lane*4 + r), then coalesced writeout
        {
            int ci = wid * CPW;
            *reinterpret_cast<float4*>(&acc_s[ci][lane * 4]) =
                make_float4(a0[0], a0[1], a0[2], a0[3]);
            *reinterpret_cast<float4*>(&acc_s[ci + 1][lane * 4]) =
                make_float4(a1[0], a1[1], a1[2], a1[3]);
        }
        __syncthreads();

        for (int idx = tid; idx < CELLS_PB * NPLANE; idx += 256) {
            int plane = idx >> 4;                   // 16 cells per segment
            int ci = idx & (CELLS_PB - 1);
            out[(size_t)plane * NOUT + cell0 + ci] = acc_s[ci][plane];
        }
        __syncthreads();                            // protect acc_s for next tile
    }
}

// ---------------------------------------------------------------
extern "C" void kernel_launch(void* const* d_in, const int* in_sizes, int n_in,
                              void* d_out, int out_size) {
    const float*  x    = (const float*)d_in[0];
    const float2* smap = (const float2*)d_in[1];
    float*        out  = (float*)d_out;

    txh_k<<<NPIX / 64, 256>>>(x, smap);
    scanA_k<<<512, 1024>>>();
    scatter_k<<<NPIX / 256, 256>>>(smap);
    gather_k<<<GATHER_GRID, 256>>>(out);
}

// round 14
// speedup vs baseline: 1.3264x; 1.3264x over previous
#include <cuda_runtime.h>
#include <cuda_fp16.h>

// Problem constants (fixed by the dataset)
#define HH   512
#define WW   1024
#define HOo  512
#define WOo  1024
#define NPIX (HH * WW)          // 524288 input pixels
#define NOUT (HOo * WOo)        // 524288 output cells per plane
#define NPLANE 128              // B*C
#define CPW  2                  // cells per warp (consecutive in x)
#define CELLS_PB 16             // 8 warps x 2 cells (x-window per block)
#define TY   8                  // output rows rolled per block
#define ROWSLAB 2048            // fixed entry slab per output row (mean ~1024, max ~1150)

// ---- static device scratch ----
__device__ __half g_xt[(size_t)NPIX * NPLANE]; // 128MB transposed x [pixel][plane], fp16
__device__ int    g_count[NOUT];               // zero at start; scanA re-zeroes each run
__device__ int    g_off[NOUT];                 // row-local exclusive scan
__device__ int    g_cursor[NOUT];
__device__ int4   g_entry[512 * ROWSLAB];      // 16MB slab-allocated entries

// ---------------------------------------------------------------
// K1: fused transpose + histogram.
__global__ __launch_bounds__(256)
void txh_k(const float* __restrict__ x, const float2* __restrict__ smap) {
    __shared__ __half hbuf[64][132];            // stride 132: uint2-aligned, low conflict
    int p0 = blockIdx.x * 64;
    int tid = threadIdx.x;

    if (tid < 64) {
        float2 s = __ldg(&smap[p0 + tid]);
        int x0 = (int)floorf(s.x);
        int y0 = (int)floorf(s.y);
        atomicAdd(&g_count[(y0 << 10) + x0], 1);
    }

    #pragma unroll
    for (int it = 0; it < 32; it++) {
        int idx = tid + it * 256;               // 0..8191
        int c  = idx >> 6;                      // plane 0..127
        int px = idx & 63;
        hbuf[px][c] = __float2half(__ldg(&x[(size_t)c * NPIX + p0 + px]));
    }
    __syncthreads();

    int lane = tid & 31, wid = tid >> 5;
    #pragma unroll
    for (int i = wid; i < 64; i += 8) {
        uint2 v = *reinterpret_cast<uint2*>(&hbuf[i][lane * 4]);
        *reinterpret_cast<uint2*>(&g_xt[(size_t)(p0 + i) * NPLANE + lane * 4]) = v;
    }
}

// K2: per-row exclusive scan -> row-local offsets + cursors; self-cleaning.
__global__ __launch_bounds__(1024)
void scanA_k() {
    int tid = threadIdx.x;
    int cell = blockIdx.x * 1024 + tid;
    int cnt = g_count[cell];
    g_count[cell] = 0;
    int lane = tid & 31, wid = tid >> 5;
    int v = cnt;
    #pragma unroll
    for (int d = 1; d < 32; d <<= 1) {
        int t = __shfl_up_sync(0xFFFFFFFFu, v, d);
        if (lane >= d) v += t;
    }
    __shared__ int wsum[32];
    if (lane == 31) wsum[wid] = v;
    __syncthreads();
    if (wid == 0) {
        int s = wsum[lane];
        #pragma unroll
        for (int d = 1; d < 32; d <<= 1) {
            int t = __shfl_up_sync(0xFFFFFFFFu, s, d);
            if (lane >= d) s += t;
        }
        wsum[lane] = s;
    }
    __syncthreads();
    int excl = v - cnt + (wid ? wsum[wid - 1] : 0);
    g_off[cell] = excl;
    g_cursor[cell] = excl;
}

// K3: scatter one entry per pixel into its row slab
__global__ __launch_bounds__(256)
void scatter_k(const float2* __restrict__ smap) {
    int p = blockIdx.x * blockDim.x + threadIdx.x;
    if (p >= NPIX) return;
    float2 s = __ldg(&smap[p]);
    float x0f = floorf(s.x), y0f = floorf(s.y);
    int x0 = (int)x0f, y0 = (int)y0f;
    float wx = s.x - x0f, wy = s.y - y0f;
    int pos = atomicAdd(&g_cursor[(y0 << 10) + x0], 1) + (y0 << 11);
    g_entry[pos] = make_int4(x0, p, __float_as_int(wx), __float_as_int(wy));
}

// K4: rolling-y gather. Block owns a 16-cell x-window x TY output rows.
// Walk anchor rows once; each entry feeds BOTH adjacent output rows via
// two rolling accumulator sets -> entry/row loads + decode per pixel halve
// vs the per-tile version (FMA count unchanged). Writeout per completed row.
__global__ __launch_bounds__(256)
void gather_k(float* __restrict__ out) {
    __shared__ float acc_s[CELLS_PB][NPLANE + 4];   // 528B stride: float4-aligned
    int tid = threadIdx.x;
    int lane = tid & 31, wid = tid >> 5;            // 8 warps
    int bx = blockIdx.x & 63;                       // 64 x-windows
    int by = blockIdx.x >> 6;                       // 64 y-groups (512/TY)
    int cellx0 = bx * CELLS_PB;
    int ystart = by * TY;
    int cx0 = cellx0 + wid * CPW;

    int xs = max(cx0 - 1, 0);
    int xe = min(cx0 + CPW - 1, WOo - 2);           // anchors exist in [0,1022]

    float lo0[4] = {0.f,0.f,0.f,0.f}, lo1[4] = {0.f,0.f,0.f,0.f};  // output row ay
    float hi0[4] = {0.f,0.f,0.f,0.f}, hi1[4] = {0.f,0.f,0.f,0.f};  // output row ay+1

    #pragma unroll 1
    for (int ay = ystart - 1; ay <= ystart + TY - 1; ay++) {
        if ((unsigned)ay <= (unsigned)(HOo - 2)) {  // anchor rows 0..510
            int rb = ay << 10;
            int o0 = __ldg(&g_off[rb + xs]);
            int o1 = __ldg(&g_off[rb + xe + 1]);
            int beg = o0 + (ay << 11);
            int end = o1 + (ay << 11);
            #pragma unroll 2
            for (int i = beg; i < end; i++) {
                int4 e = __ldg(&g_entry[i]);
                uint2 r = __ldg(reinterpret_cast<const uint2*>(
                    &g_xt[(size_t)e.y * NPLANE + lane * 4]));
                float wx = __int_as_float(e.z);
                float wy = __int_as_float(e.w);
                float omx = 1.0f - wx;
                float omy = 1.0f - wy;
                int d = e.x - cx0;                  // -1, 0, 1
                float w0 = (d == 0) ? omx : ((d == -1) ? wx : 0.0f);
                float w1 = (d == 1) ? omx : ((d == 0) ? wx : 0.0f);
                float wl0 = w0 * omy, wl1 = w1 * omy;   // -> output row ay
                float wh0 = w0 * wy,  wh1 = w1 * wy;    // -> output row ay+1
                float2 f0 = __half22float2(*reinterpret_cast<__half2*>(&r.x));
                float2 f1 = __half22float2(*reinterpret_cast<__half2*>(&r.y));
                lo0[0] = fmaf(wl0, f0.x, lo0[0]);
                lo0[1] = fmaf(wl0, f0.y, lo0[1]);
                lo0[2] = fmaf(wl0, f1.x, lo0[2]);
                lo0[3] = fmaf(wl0, f1.y, lo0[3]);
                lo1[0] = fmaf(wl1, f0.x, lo1[0]);
                lo1[1] = fmaf(wl1, f0.y, lo1[1]);
                lo1[2] = fmaf(wl1, f1.x, lo1[2]);
                lo1[3] = fmaf(wl1, f1.y, lo1[3]);
                hi0[0] = fmaf(wh0, f0.x, hi0[0]);
                hi0[1] = fmaf(wh0, f0.y, hi0[1]);
                hi0[2] = fmaf(wh0, f1.x, hi0[2]);
                hi0[3] = fmaf(wh0, f1.y, hi0[3]);
                hi1[0] = fmaf(wh1, f0.x, hi1[0]);
                hi1[1] = fmaf(wh1, f0.y, hi1[1]);
                hi1[2] = fmaf(wh1, f1.x, hi1[2]);
                hi1[3] = fmaf(wh1, f1.y, hi1[3]);
            }
        }

        // output row ay is now complete in lo (wy part arrived last step)
        if (ay >= ystart) {
            int ci = wid * CPW;
            *reinterpret_cast<float4*>(&acc_s[ci][lane * 4]) =
                make_float4(lo0[0], lo0[1], lo0[2], lo0[3]);
            *reinterpret_cast<float4*>(&acc_s[ci + 1][lane * 4]) =
                make_float4(lo1[0], lo1[1], lo1[2], lo1[3]);
            __syncthreads();
            size_t rowbase = (size_t)ay * WOo + cellx0;
            for (int idx = tid; idx < CELLS_PB * NPLANE; idx += 256) {
                int plane = idx >> 4;               // 16 cells per x-window
                int c = idx & (CELLS_PB - 1);
                out[(size_t)plane * NOUT + rowbase + c] = acc_s[c][plane];
            }
            __syncthreads();                        // protect acc_s for next step
        }

        // rotate accumulators: lo <- hi, hi <- 0
        #pragma unroll
        for (int rreg = 0; rreg < 4; rreg++) {
            lo0[rreg] = hi0[rreg]; lo1[rreg] = hi1[rreg];
            hi0[rreg] = 0.0f;      hi1[rreg] = 0.0f;
        }
    }
}

// ---------------------------------------------------------------
extern "C" void kernel_launch(void* const* d_in, const int* in_sizes, int n_in,
                              void* d_out, int out_size) {
    const float*  x    = (const float*)d_in[0];
    const float2* smap = (const float2*)d_in[1];
    float*        out  = (float*)d_out;

    txh_k<<<NPIX / 64, 256>>>(x, smap);
    scanA_k<<<512, 1024>>>();
    scatter_k<<<NPIX / 256, 256>>>(smap);
    gather_k<<<64 * (HOo / TY), 256>>>(out);
}

// round 15
// speedup vs baseline: 1.3320x; 1.0042x over previous
#include <cuda_runtime.h>
#include <cuda_fp16.h>

// Problem constants (fixed by the dataset)
#define HH   512
#define WW   1024
#define HOo  512
#define WOo  1024
#define NPIX (HH * WW)          // 524288 input pixels
#define NOUT (HOo * WOo)        // 524288 output cells per plane
#define NPLANE 128              // B*C
#define CPW  2                  // cells per warp (consecutive in x)
#define CELLS_PB 16             // 8 warps x 2 cells per block (one row segment)
#define ROWSLAB 2048            // fixed entry slab per output row (mean ~1024, max ~1150)

// ---- static device scratch ----
__device__ __half g_xt[(size_t)NPIX * NPLANE]; // 128MB transposed x [pixel][plane], fp16
__device__ int    g_count[NOUT];               // zero at start; scanA re-zeroes each run
__device__ int    g_off[NOUT];                 // row-local exclusive scan
__device__ int    g_cursor[NOUT];
__device__ int4   g_entry[512 * ROWSLAB];      // 16MB slab-allocated entries

// ---------------------------------------------------------------
// K1: fused transpose + histogram.
__global__ __launch_bounds__(256)
void txh_k(const float* __restrict__ x, const float2* __restrict__ smap) {
    __shared__ __half hbuf[64][132];            // stride 132: uint2-aligned, low conflict
    int p0 = blockIdx.x * 64;
    int tid = threadIdx.x;

    if (tid < 64) {
        float2 s = __ldg(&smap[p0 + tid]);
        int x0 = (int)floorf(s.x);
        int y0 = (int)floorf(s.y);
        atomicAdd(&g_count[(y0 << 10) + x0], 1);
    }

    #pragma unroll
    for (int it = 0; it < 32; it++) {
        int idx = tid + it * 256;               // 0..8191
        int c  = idx >> 6;                      // plane 0..127
        int px = idx & 63;
        hbuf[px][c] = __float2half(__ldg(&x[(size_t)c * NPIX + p0 + px]));
    }
    __syncthreads();

    int lane = tid & 31, wid = tid >> 5;
    #pragma unroll
    for (int i = wid; i < 64; i += 8) {
        uint2 v = *reinterpret_cast<uint2*>(&hbuf[i][lane * 4]);
        *reinterpret_cast<uint2*>(&g_xt[(size_t)(p0 + i) * NPLANE + lane * 4]) = v;
    }
}

// K2: per-row exclusive scan -> row-local offsets + cursors; self-cleaning.
__global__ __launch_bounds__(1024)
void scanA_k() {
    int tid = threadIdx.x;
    int cell = blockIdx.x * 1024 + tid;
    int cnt = g_count[cell];
    g_count[cell] = 0;
    int lane = tid & 31, wid = tid >> 5;
    int v = cnt;
    #pragma unroll
    for (int d = 1; d < 32; d <<= 1) {
        int t = __shfl_up_sync(0xFFFFFFFFu, v, d);
        if (lane >= d) v += t;
    }
    __shared__ int wsum[32];
    if (lane == 31) wsum[wid] = v;
    __syncthreads();
    if (wid == 0) {
        int s = wsum[lane];
        #pragma unroll
        for (int d = 1; d < 32; d <<= 1) {
            int t = __shfl_up_sync(0xFFFFFFFFu, s, d);
            if (lane >= d) s += t;
        }
        wsum[lane] = s;
    }
    __syncthreads();
    int excl = v - cnt + (wid ? wsum[wid - 1] : 0);
    g_off[cell] = excl;
    g_cursor[cell] = excl;
}

// K3: scatter one entry per pixel into its row slab
__global__ __launch_bounds__(256)
void scatter_k(const float2* __restrict__ smap) {
    int p = blockIdx.x * blockDim.x + threadIdx.x;
    if (p >= NPIX) return;
    float2 s = __ldg(&smap[p]);
    float x0f = floorf(s.x), y0f = floorf(s.y);
    int x0 = (int)x0f, y0 = (int)y0f;
    float wx = s.x - x0f, wy = s.y - y0f;
    int pos = atomicAdd(&g_cursor[(y0 << 10) + x0], 1) + (y0 << 11);
    g_entry[pos] = make_int4(x0, p, __float_as_int(wx), __float_as_int(wy));
}

// K4: gather with the dependent-load chain broken:
//  A) 32 threads cooperatively prefetch ALL per-warp g_off endpoints (1 trip)
//  B) each warp stages its merged entry list lane-cooperatively into smem
//     (1 coalesced trip, y-weight folded, zero-weight dummy padding)
//  C) hot loop: LDS-broadcast metas + 4 row LDGs in flight, no clamps.
__global__ __launch_bounds__(256)
void gather_k(float* __restrict__ out) {
    __shared__ float acc_s[CELLS_PB][NPLANE + 4];   // 528B stride: float4-aligned
    __shared__ int   s_off[8][4];                   // per warp: beg0,end0,beg1,end1
    __shared__ int4  s_meta[8][32];                 // warp-private staged entries
    int tid = threadIdx.x;
    int lane = tid & 31, wid = tid >> 5;            // 8 warps
    int cell0 = blockIdx.x * CELLS_PB;              // 16-aligned -> one row
    int cy = cell0 >> 10;
    int cx0 = (cell0 & 1023) + wid * CPW;

    // Phase A: cooperative g_off prefetch (8 warps x {beg0,end0,beg1,end1})
    if (tid < 32) {
        int w = tid >> 2, q = tid & 3;
        int rr = q >> 1, side = q & 1;
        int ay = cy - 1 + rr;
        int val = 0;
        if ((unsigned)ay <= (unsigned)(HOo - 2)) {  // anchor rows 0..510
            int cxw = (cell0 & 1023) + w * CPW;
            int xsw = max(cxw - 1, 0);
            int xew = min(cxw + CPW - 1, WOo - 2);
            int col = side ? (xew + 1) : xsw;
            val = __ldg(&g_off[(ay << 10) + col]) + (ay << 11);
        }
        s_off[w][q] = val;
    }
    __syncthreads();

    int beg0 = s_off[wid][0], end0 = s_off[wid][1];
    int beg1 = s_off[wid][2], end1 = s_off[wid][3];
    int n0 = end0 - beg0, n1 = end1 - beg1;
    int total = n0 + n1;
    int tclamp = min(total, 32);

    // Phase B: stage entries (lane l -> entry l), fold y-weight, pad with
    // zero-weight dummies so the hot loop needs no guards.
    {
        int4 e = make_int4(cx0, 0, 0, 0);           // dummy: pixel 0, weight 0
        if (lane < tclamp) {
            bool r0 = lane < n0;                    // row cy-1 -> weight wy
            int gi = r0 ? (beg0 + lane) : (beg1 + lane - n0);
            e = __ldg(&g_entry[gi]);
            float wy = __int_as_float(e.w);
            e.w = __float_as_int(r0 ? wy : (1.0f - wy));
        }
        s_meta[wid][lane] = e;
    }
    __syncwarp();

    float a0[4] = {0.f, 0.f, 0.f, 0.f};             // cell cx0
    float a1[4] = {0.f, 0.f, 0.f, 0.f};             // cell cx0+1

    auto process = [&](int4 e, uint2 r) {
        float wx = __int_as_float(e.z);
        float wyv = __int_as_float(e.w);
        float omx = 1.0f - wx;
        int d = e.x - cx0;                          // -1, 0, 1
        float w0 = (d == 0) ? omx : ((d == -1) ? wx : 0.0f);
        float w1 = (d == 1) ? omx : ((d == 0) ? wx : 0.0f);
        w0 *= wyv;
        w1 *= wyv;
        float2 f0 = __half22float2(*reinterpret_cast<__half2*>(&r.x));
        float2 f1 = __half22float2(*reinterpret_cast<__half2*>(&r.y));
        a0[0] = fmaf(w0, f0.x, a0[0]);
        a0[1] = fmaf(w0, f0.y, a0[1]);
        a0[2] = fmaf(w0, f1.x, a0[2]);
        a0[3] = fmaf(w0, f1.y, a0[3]);
        a1[0] = fmaf(w1, f0.x, a1[0]);
        a1[1] = fmaf(w1, f0.y, a1[1]);
        a1[2] = fmaf(w1, f1.x, a1[2]);
        a1[3] = fmaf(w1, f1.y, a1[3]);
    };

    // Phase C: 4-wide chunks; metas from smem (broadcast), 4 rows in flight.
    int nproc = (tclamp + 3) & ~3;                  // <= 32; dummies are 0-weight
    #pragma unroll 1
    for (int base = 0; base < nproc; base += 4) {
        int4 e0 = s_meta[wid][base];
        int4 e1 = s_meta[wid][base + 1];
        int4 e2 = s_meta[wid][base + 2];
        int4 e3 = s_meta[wid][base + 3];
        uint2 r0 = __ldg(reinterpret_cast<const uint2*>(
            &g_xt[(size_t)e0.y * NPLANE + lane * 4]));
        uint2 r1 = __ldg(reinterpret_cast<const uint2*>(
            &g_xt[(size_t)e1.y * NPLANE + lane * 4]));
        uint2 r2 = __ldg(reinterpret_cast<const uint2*>(
            &g_xt[(size_t)e2.y * NPLANE + lane * 4]));
        uint2 r3 = __ldg(reinterpret_cast<const uint2*>(
            &g_xt[(size_t)e3.y * NPLANE + lane * 4]));
        process(e0, r0);
        process(e1, r1);
        process(e2, r2);
        process(e3, r3);
    }

    // astronomically-rare tail (total > 32): direct fallback
    #pragma unroll 1
    for (int k = 32; k < total; k++) {
        bool r0k = k < n0;
        int gi = r0k ? (beg0 + k) : (beg1 + k - n0);
        int4 e = __ldg(&g_entry[gi]);
        float wy = __int_as_float(e.w);
        e.w = __float_as_int(r0k ? wy : (1.0f - wy));
        uint2 r = __ldg(reinterpret_cast<const uint2*>(
            &g_xt[(size_t)e.y * NPLANE + lane * 4]));
        process(e, r);
    }

    // stage to shared (plane = lane*4 + r), then coalesced writeout
    {
        int ci = wid * CPW;
        *reinterpret_cast<float4*>(&acc_s[ci][lane * 4]) =
            make_float4(a0[0], a0[1], a0[2], a0[3]);
        *reinterpret_cast<float4*>(&acc_s[ci + 1][lane * 4]) =
            make_float4(a1[0], a1[1], a1[2], a1[3]);
    }
    __syncthreads();

    for (int idx = tid; idx < CELLS_PB * NPLANE; idx += 256) {
        int plane = idx >> 4;                       // 16 cells per segment
        int ci = idx & (CELLS_PB - 1);
        out[(size_t)plane * NOUT + cell0 + ci] = acc_s[ci][plane];
    }
}

// ---------------------------------------------------------------
extern "C" void kernel_launch(void* const* d_in, const int* in_sizes, int n_in,
                              void* d_out, int out_size) {
    const float*  x    = (const float*)d_in[0];
    const float2* smap = (const float2*)d_in[1];
    float*        out  = (float*)d_out;

    txh_k<<<NPIX / 64, 256>>>(x, smap);
    scanA_k<<<512, 1024>>>();
    scatter_k<<<NPIX / 256, 256>>>(smap);
    gather_k<<<NOUT / CELLS_PB, 256>>>(out);
}

// round 16
// speedup vs baseline: 1.3387x; 1.0050x over previous
#include <cuda_runtime.h>
#include <cuda_fp16.h>

// Problem constants (fixed by the dataset)
#define HH   512
#define WW   1024
#define HOo  512
#define WOo  1024
#define NPIX (HH * WW)          // 524288 input pixels
#define NOUT (HOo * WOo)        // 524288 output cells per plane
#define NPLANE 128              // B*C
#define CPW  2                  // cells per warp (consecutive in x)
#define CELLS_PB 16             // 8 warps x 2 cells per block (one row segment)
#define ROWSLAB 2048            // fixed entry slab per output row (mean ~1024, max ~1150)

// ---- static device scratch ----
__device__ __half g_xt[(size_t)NPIX * NPLANE]; // 128MB transposed x [pixel][plane], fp16
__device__ int    g_count[NOUT];               // zero at start; scanA re-zeroes each run
__device__ int    g_off[NOUT];                 // row-local exclusive scan
__device__ int    g_cursor[NOUT];
__device__ int4   g_entry[512 * ROWSLAB];      // 16MB slab-allocated entries

// ---------------------------------------------------------------
// K1: fused transpose + histogram.
// x is read STREAMING (__ldcs) so the 256MB single-use input does not
// evict the freshly-written g_xt lines — g_xt (128MB ~ L2 126MB) must be
// L2-resident when the gather runs.
__global__ __launch_bounds__(256)
void txh_k(const float* __restrict__ x, const float2* __restrict__ smap) {
    __shared__ __half hbuf[64][132];            // stride 132: uint2-aligned, low conflict
    int p0 = blockIdx.x * 64;
    int tid = threadIdx.x;

    if (tid < 64) {
        float2 s = __ldcs(&smap[p0 + tid]);
        int x0 = (int)floorf(s.x);
        int y0 = (int)floorf(s.y);
        atomicAdd(&g_count[(y0 << 10) + x0], 1);
    }

    #pragma unroll
    for (int it = 0; it < 32; it++) {
        int idx = tid + it * 256;               // 0..8191
        int c  = idx >> 6;                      // plane 0..127
        int px = idx & 63;
        hbuf[px][c] = __float2half(__ldcs(&x[(size_t)c * NPIX + p0 + px]));
    }
    __syncthreads();

    // g_xt store: DEFAULT policy (evict_normal) -> stays resident in L2
    int lane = tid & 31, wid = tid >> 5;
    #pragma unroll
    for (int i = wid; i < 64; i += 8) {
        uint2 v = *reinterpret_cast<uint2*>(&hbuf[i][lane * 4]);
        *reinterpret_cast<uint2*>(&g_xt[(size_t)(p0 + i) * NPLANE + lane * 4]) = v;
    }
}

// K2: per-row exclusive scan -> row-local offsets + cursors; self-cleaning.
__global__ __launch_bounds__(1024)
void scanA_k() {
    int tid = threadIdx.x;
    int cell = blockIdx.x * 1024 + tid;
    int cnt = g_count[cell];
    g_count[cell] = 0;
    int lane = tid & 31, wid = tid >> 5;
    int v = cnt;
    #pragma unroll
    for (int d = 1; d < 32; d <<= 1) {
        int t = __shfl_up_sync(0xFFFFFFFFu, v, d);
        if (lane >= d) v += t;
    }
    __shared__ int wsum[32];
    if (lane == 31) wsum[wid] = v;
    __syncthreads();
    if (wid == 0) {
        int s = wsum[lane];
        #pragma unroll
        for (int d = 1; d < 32; d <<= 1) {
            int t = __shfl_up_sync(0xFFFFFFFFu, s, d);
            if (lane >= d) s += t;
        }
        wsum[lane] = s;
    }
    __syncthreads();
    int excl = v - cnt + (wid ? wsum[wid - 1] : 0);
    g_off[cell] = excl;
    g_cursor[cell] = excl;
}

// K3: scatter one entry per pixel into its row slab.
// smap read streaming; entry store streaming (evict-first) so the 8MB
// entry write-stream does not evict resident g_xt.
__global__ __launch_bounds__(256)
void scatter_k(const float2* __restrict__ smap) {
    int p = blockIdx.x * blockDim.x + threadIdx.x;
    if (p >= NPIX) return;
    float2 s = __ldcs(&smap[p]);
    float x0f = floorf(s.x), y0f = floorf(s.y);
    int x0 = (int)x0f, y0 = (int)y0f;
    float wx = s.x - x0f, wy = s.y - y0f;
    int pos = atomicAdd(&g_cursor[(y0 << 10) + x0], 1) + (y0 << 11);
    __stcs(&g_entry[pos], make_int4(x0, p, __float_as_int(wx), __float_as_int(wy)));
}

// K4: gather (R15 structure). Cache-policy changes only:
//  - entry reads __ldcs (streaming; short-range re-reads still hit)
//  - out writes __stcs (evict-first: the 256MB write stream churns in a
//    small pool instead of flushing x_t out of L2)
//  - row reads default -> should now be L2 hits on resident g_xt.
__global__ __launch_bounds__(256)
void gather_k(float* __restrict__ out) {
    __shared__ float acc_s[CELLS_PB][NPLANE + 4];   // 528B stride: float4-aligned
    __shared__ int   s_off[8][4];                   // per warp: beg0,end0,beg1,end1
    __shared__ int4  s_meta[8][32];                 // warp-private staged entries
    int tid = threadIdx.x;
    int lane = tid & 31, wid = tid >> 5;            // 8 warps
    int cell0 = blockIdx.x * CELLS_PB;              // 16-aligned -> one row
    int cy = cell0 >> 10;
    int cx0 = (cell0 & 1023) + wid * CPW;

    // Phase A: cooperative g_off prefetch (8 warps x {beg0,end0,beg1,end1})
    if (tid < 32) {
        int w = tid >> 2, q = tid & 3;
        int rr = q >> 1, side = q & 1;
        int ay = cy - 1 + rr;
        int val = 0;
        if ((unsigned)ay <= (unsigned)(HOo - 2)) {  // anchor rows 0..510
            int cxw = (cell0 & 1023) + w * CPW;
            int xsw = max(cxw - 1, 0);
            int xew = min(cxw + CPW - 1, WOo - 2);
            int col = side ? (xew + 1) : xsw;
            val = __ldg(&g_off[(ay << 10) + col]) + (ay << 11);
        }
        s_off[w][q] = val;
    }
    __syncthreads();

    int beg0 = s_off[wid][0], end0 = s_off[wid][1];
    int beg1 = s_off[wid][2], end1 = s_off[wid][3];
    int n0 = end0 - beg0, n1 = end1 - beg1;
    int total = n0 + n1;
    int tclamp = min(total, 32);

    // Phase B: stage entries (lane l -> entry l), fold y-weight, pad with
    // zero-weight dummies so the hot loop needs no guards.
    {
        int4 e = make_int4(cx0, 0, 0, 0);           // dummy: pixel 0, weight 0
        if (lane < tclamp) {
            bool r0 = lane < n0;                    // row cy-1 -> weight wy
            int gi = r0 ? (beg0 + lane) : (beg1 + lane - n0);
            e = __ldcs(&g_entry[gi]);
            float wy = __int_as_float(e.w);
            e.w = __float_as_int(r0 ? wy : (1.0f - wy));
        }
        s_meta[wid][lane] = e;
    }
    __syncwarp();

    float a0[4] = {0.f, 0.f, 0.f, 0.f};             // cell cx0
    float a1[4] = {0.f, 0.f, 0.f, 0.f};             // cell cx0+1

    auto process = [&](int4 e, uint2 r) {
        float wx = __int_as_float(e.z);
        float wyv = __int_as_float(e.w);
        float omx = 1.0f - wx;
        int d = e.x - cx0;                          // -1, 0, 1
        float w0 = (d == 0) ? omx : ((d == -1) ? wx : 0.0f);
        float w1 = (d == 1) ? omx : ((d == 0) ? wx : 0.0f);
        w0 *= wyv;
        w1 *= wyv;
        float2 f0 = __half22float2(*reinterpret_cast<__half2*>(&r.x));
        float2 f1 = __half22float2(*reinterpret_cast<__half2*>(&r.y));
        a0[0] = fmaf(w0, f0.x, a0[0]);
        a0[1] = fmaf(w0, f0.y, a0[1]);
        a0[2] = fmaf(w0, f1.x, a0[2]);
        a0[3] = fmaf(w0, f1.y, a0[3]);
        a1[0] = fmaf(w1, f0.x, a1[0]);
        a1[1] = fmaf(w1, f0.y, a1[1]);
        a1[2] = fmaf(w1, f1.x, a1[2]);
        a1[3] = fmaf(w1, f1.y, a1[3]);
    };

    // Phase C: 4-wide chunks; metas from smem (broadcast), 4 rows in flight.
    int nproc = (tclamp + 3) & ~3;                  // <= 32; dummies are 0-weight
    #pragma unroll 1
    for (int base = 0; base < nproc; base += 4) {
        int4 e0 = s_meta[wid][base];
        int4 e1 = s_meta[wid][base + 1];
        int4 e2 = s_meta[wid][base + 2];
        int4 e3 = s_meta[wid][base + 3];
        uint2 r0 = __ldg(reinterpret_cast<const uint2*>(
            &g_xt[(size_t)e0.y * NPLANE + lane * 4]));
        uint2 r1 = __ldg(reinterpret_cast<const uint2*>(
            &g_xt[(size_t)e1.y * NPLANE + lane * 4]));
        uint2 r2 = __ldg(reinterpret_cast<const uint2*>(
            &g_xt[(size_t)e2.y * NPLANE + lane * 4]));
        uint2 r3 = __ldg(reinterpret_cast<const uint2*>(
            &g_xt[(size_t)e3.y * NPLANE + lane * 4]));
        process(e0, r0);
        process(e1, r1);
        process(e2, r2);
        process(e3, r3);
    }

    // astronomically-rare tail (total > 32): direct fallback
    #pragma unroll 1
    for (int k = 32; k < total; k++) {
        bool r0k = k < n0;
        int gi = r0k ? (beg0 + k) : (beg1 + k - n0);
        int4 e = __ldcs(&g_entry[gi]);
        float wy = __int_as_float(e.w);
        e.w = __float_as_int(r0k ? wy : (1.0f - wy));
        uint2 r = __ldg(reinterpret_cast<const uint2*>(
            &g_xt[(size_t)e.y * NPLANE + lane * 4]));
        process(e, r);
    }

    // stage to shared (plane = lane*4 + r), then coalesced STREAMING writeout
    {
        int ci = wid * CPW;
        *reinterpret_cast<float4*>(&acc_s[ci][lane * 4]) =
            make_float4(a0[0], a0[1], a0[2], a0[3]);
        *reinterpret_cast<float4*>(&acc_s[ci + 1][lane * 4]) =
            make_float4(a1[0], a1[1], a1[2], a1[3]);
    }
    __syncthreads();

    for (int idx = tid; idx < CELLS_PB * NPLANE; idx += 256) {
        int plane = idx >> 4;                       // 16 cells per segment
        int ci = idx & (CELLS_PB - 1);
        __stcs(&out[(size_t)plane * NOUT + cell0 + ci], acc_s[ci][plane]);
    }
}

// ---------------------------------------------------------------
extern "C" void kernel_launch(void* const* d_in, const int* in_sizes, int n_in,
                              void* d_out, int out_size) {
    const float*  x    = (const float*)d_in[0];
    const float2* smap = (const float2*)d_in[1];
    float*        out  = (float*)d_out;

    txh_k<<<NPIX / 64, 256>>>(x, smap);
    scanA_k<<<512, 1024>>>();
    scatter_k<<<NPIX / 256, 256>>>(smap);
    gather_k<<<NOUT / CELLS_PB, 256>>>(out);
}